// round 7
// baseline (speedup 1.0000x reference)
#include <cuda_runtime.h>

// Problem constants
#define BB 64
#define TT 512
#define II 512
#define HH 1024
#define GG 4096   // 4*H
#define CH 32     // k per smem chunk
#define NCH (HH / CH)
#define NBLK 128
#define NTHR 256

// ---------------------------------------------------------------------------
// Device scratch (static — no allocations allowed)
// ---------------------------------------------------------------------------
__device__ float g_xp[TT][BB][2 * GG];    // 1 GB: input projection + biases, time s
__device__ float g_hT[2][2][HH][BB];      // [parity][dir][unit(k)][b]  (transposed h)
__device__ float g_c[2][BB][HH];          // [dir][b][u]
__device__ float g_wT[2][HH][GG];         // w_hh transposed + column-permuted
__device__ unsigned g_bar;                // grid barrier arrival counter

// ---------------------------------------------------------------------------
// FFMA2 helpers (packed f32x2)
// ---------------------------------------------------------------------------
__device__ __forceinline__ unsigned long long pk2(float lo, float hi) {
    unsigned long long r;
    asm("mov.b64 %0, {%1, %2};" : "=l"(r) : "f"(lo), "f"(hi));
    return r;
}
__device__ __forceinline__ void fma2(unsigned long long& d,
                                     unsigned long long a, unsigned long long b) {
    asm("fma.rn.f32x2 %0, %1, %2, %0;" : "+l"(d) : "l"(a), "l"(b));
}
__device__ __forceinline__ float2 upk(unsigned long long v) {
    float2 f;
    asm("mov.b64 {%0, %1}, %2;" : "=f"(f.x), "=f"(f.y) : "l"(v));
    return f;
}
__device__ __forceinline__ float sigm(float x) {
    return 1.f / (1.f + __expf(-x));
}

// ---------------------------------------------------------------------------
__global__ void init_state() {
    int idx = blockIdx.x * blockDim.x + threadIdx.x;
    const int n_h = 2 * 2 * HH * BB;
    const int n_c = 2 * BB * HH;
    if (idx < n_h) ((float*)g_hT)[idx] = 0.f;
    if (idx < n_c) ((float*)g_c)[idx] = 0.f;
    if (idx == 0) g_bar = 0u;
}

// ---------------------------------------------------------------------------
// One-time w_hh transpose into g_wT[dir][k][pc]:
//   pc = ublock*64 + q*16 + u  <->  src_row = q*H + ublock*16 + u
// ---------------------------------------------------------------------------
__global__ void transpose_w(const float* __restrict__ fw,
                            const float* __restrict__ bw) {
    int idx = blockIdx.x * blockDim.x + threadIdx.x;
    if (idx >= 2 * HH * GG) return;
    int dir = idx / (HH * GG);
    int rem = idx % (HH * GG);
    int k  = rem / GG;
    int pc = rem % GG;
    int ublock = pc >> 6;
    int r2 = pc & 63;
    int q = r2 >> 4;
    int u = r2 & 15;
    int src_row = q * HH + ublock * 16 + u;
    const float* w = dir ? bw : fw;
    g_wT[dir][k][pc] = w[(size_t)src_row * HH + k];
}

// ---------------------------------------------------------------------------
// xp GEMM with column-packed FFMA2:
//   g_xp[s][b][dir*4096+n] = x @ w_ih^T + biases
// ---------------------------------------------------------------------------
__global__ __launch_bounds__(256) void xp_gemm(
    const float* __restrict__ x,
    const float* __restrict__ w_fw, const float* __restrict__ w_bw,
    const float* __restrict__ bih_fw, const float* __restrict__ bhh_fw,
    const float* __restrict__ bih_bw, const float* __restrict__ bhh_bw)
{
    const int dir = blockIdx.z;
    const float* __restrict__ w  = dir ? w_bw  : w_fw;
    const float* __restrict__ bi = dir ? bih_bw : bih_fw;
    const float* __restrict__ bh = dir ? bhh_bw : bhh_fw;
    const int n0 = blockIdx.x * 128;
    const int m0 = blockIdx.y * 128;

    __shared__ __align__(16) float As[16][128];
    __shared__ __align__(16) float Bs[16][128];

    const int tid = threadIdx.x;
    const int tx = tid & 15;
    const int ty = tid >> 4;

    unsigned long long acc2[8][4];
    #pragma unroll
    for (int i = 0; i < 8; i++)
        #pragma unroll
        for (int j = 0; j < 4; j++) acc2[i][j] = 0ULL;

    for (int k0 = 0; k0 < II; k0 += 16) {
        #pragma unroll
        for (int it = 0; it < 2; it++) {
            int idx = tid + it * 256;
            int row = idx >> 2;
            int kv  = (idx & 3) * 4;
            int m = m0 + row;
            int s = m >> 6;
            int b = m & 63;
            float4 va = *reinterpret_cast<const float4*>(
                x + ((size_t)b * TT + s) * II + k0 + kv);
            As[kv + 0][row] = va.x; As[kv + 1][row] = va.y;
            As[kv + 2][row] = va.z; As[kv + 3][row] = va.w;
            float4 vb = *reinterpret_cast<const float4*>(
                w + (size_t)(n0 + row) * II + k0 + kv);
            Bs[kv + 0][row] = vb.x; Bs[kv + 1][row] = vb.y;
            Bs[kv + 2][row] = vb.z; Bs[kv + 3][row] = vb.w;
        }
        __syncthreads();
        #pragma unroll
        for (int kk = 0; kk < 16; kk++) {
            float4 a0 = *reinterpret_cast<const float4*>(&As[kk][ty * 8]);
            float4 a1 = *reinterpret_cast<const float4*>(&As[kk][ty * 8 + 4]);
            ulonglong2 b0 = *reinterpret_cast<const ulonglong2*>(&Bs[kk][tx * 8]);
            ulonglong2 b1 = *reinterpret_cast<const ulonglong2*>(&Bs[kk][tx * 8 + 4]);
            float a[8] = {a0.x, a0.y, a0.z, a0.w, a1.x, a1.y, a1.z, a1.w};
            #pragma unroll
            for (int i = 0; i < 8; i++) {
                unsigned long long ap = pk2(a[i], a[i]);
                fma2(acc2[i][0], ap, b0.x);
                fma2(acc2[i][1], ap, b0.y);
                fma2(acc2[i][2], ap, b1.x);
                fma2(acc2[i][3], ap, b1.y);
            }
        }
        __syncthreads();
    }

    float bias[8];
    #pragma unroll
    for (int j = 0; j < 8; j++) {
        int n = n0 + tx * 8 + j;
        bias[j] = bi[n] + bh[n];
    }
    #pragma unroll
    for (int i = 0; i < 8; i++) {
        int m = m0 + ty * 8 + i;
        int s = m >> 6;
        int b = m & 63;
        float2 p0 = upk(acc2[i][0]);
        float2 p1 = upk(acc2[i][1]);
        float2 p2 = upk(acc2[i][2]);
        float2 p3 = upk(acc2[i][3]);
        float* dst = &g_xp[s][b][dir * GG + n0 + tx * 8];
        float4 v0, v1;
        v0.x = p0.x + bias[0]; v0.y = p0.y + bias[1];
        v0.z = p1.x + bias[2]; v0.w = p1.y + bias[3];
        v1.x = p2.x + bias[4]; v1.y = p2.y + bias[5];
        v1.z = p3.x + bias[6]; v1.w = p3.y + bias[7];
        *reinterpret_cast<float4*>(dst)     = v0;
        *reinterpret_cast<float4*>(dst + 4) = v1;
    }
}

// ---------------------------------------------------------------------------
// Persistent recurrence kernel: 128 blocks x 256 threads (2 warps/SMSP).
// Block = (dir, 16 hidden units) -> 64x64 gate tile, K=1024.
// Column-packed FFMA2: per-thread tile = 2 batch x 8 cols (4 f32x2 col-pairs),
// W consumed directly from LDS.128 as packed pairs (no packs on B side).
// ---------------------------------------------------------------------------
__global__ __launch_bounds__(NTHR, 1) void lstm_persist(float* __restrict__ out)
{
    const int bid = blockIdx.x;
    const int dir = bid >> 6;
    const int ublk = bid & 63;
    const int u0 = ublk * 16;
    const int c0w = ublk * 64;
    const int tid = threadIdx.x;

    // Flat smem: Hs[2][32][64] @ 0, Ws[2][32][64] @ 4096; Gsm[64][68] aliases @ 0.
    __shared__ __align__(16) float sm[8192];
    #define HS(p, k, i) (sm + (p) * 2048 + (k) * 64 + (i))
    #define WS(p, k, i) (sm + 4096 + (p) * 2048 + (k) * 64 + (i))

    // staging map: 8 threads per k-row, 8 floats each
    const int ld_k = tid >> 3;    // 0..31
    const int ld_f = tid & 7;     // 0..7
    // compute map: cg = col-group (8 cols), ty = batch-pair group
    const int cg = tid & 7;       // cols cg*8 .. +7
    const int ty = tid >> 3;      // batches ty*2, ty*2+1
    // cell map: 4 threads per batch, 4 units each
    const int cb = tid >> 2;            // batch 0..63
    const int ub = (tid & 3) * 4;       // unit sub-range (4 units)

    for (int t = 0; t < TT; t++) {
        const int rd = t & 1;
        const int wr = rd ^ 1;

        unsigned long long acc[2][4];
        #pragma unroll
        for (int i = 0; i < 2; i++)
            #pragma unroll
            for (int j = 0; j < 4; j++) acc[i][j] = 0ULL;

        float4 hreg[2], wreg[2];

        // prologue: stage chunk 0
        hreg[0] = __ldcg((const float4*)&g_hT[rd][dir][ld_k][ld_f * 8]);
        hreg[1] = __ldcg((const float4*)&g_hT[rd][dir][ld_k][ld_f * 8 + 4]);
        wreg[0] = *(const float4*)&g_wT[dir][ld_k][c0w + ld_f * 8];
        wreg[1] = *(const float4*)&g_wT[dir][ld_k][c0w + ld_f * 8 + 4];
        *(float4*)HS(0, ld_k, ld_f * 8)     = hreg[0];
        *(float4*)HS(0, ld_k, ld_f * 8 + 4) = hreg[1];
        *(float4*)WS(0, ld_k, ld_f * 8)     = wreg[0];
        *(float4*)WS(0, ld_k, ld_f * 8 + 4) = wreg[1];
        __syncthreads();

        for (int c = 0; c < NCH; c++) {
            const int p = c & 1;
            if (c + 1 < NCH) {
                int kk = (c + 1) * CH + ld_k;
                hreg[0] = __ldcg((const float4*)&g_hT[rd][dir][kk][ld_f * 8]);
                hreg[1] = __ldcg((const float4*)&g_hT[rd][dir][kk][ld_f * 8 + 4]);
                wreg[0] = *(const float4*)&g_wT[dir][kk][c0w + ld_f * 8];
                wreg[1] = *(const float4*)&g_wT[dir][kk][c0w + ld_f * 8 + 4];
            }
            #pragma unroll
            for (int k = 0; k < CH; k++) {
                float2 hv = *(const float2*)HS(p, k, ty * 2);
                ulonglong2 w0 = *(const ulonglong2*)WS(p, k, cg * 8);
                ulonglong2 w1 = *(const ulonglong2*)WS(p, k, cg * 8 + 4);
                unsigned long long a0 = pk2(hv.x, hv.x);
                unsigned long long a1 = pk2(hv.y, hv.y);
                fma2(acc[0][0], a0, w0.x); fma2(acc[0][1], a0, w0.y);
                fma2(acc[0][2], a0, w1.x); fma2(acc[0][3], a0, w1.y);
                fma2(acc[1][0], a1, w0.x); fma2(acc[1][1], a1, w0.y);
                fma2(acc[1][2], a1, w1.x); fma2(acc[1][3], a1, w1.y);
            }
            if (c + 1 < NCH) {
                __syncthreads();
                const int pn = p ^ 1;
                *(float4*)HS(pn, ld_k, ld_f * 8)     = hreg[0];
                *(float4*)HS(pn, ld_k, ld_f * 8 + 4) = hreg[1];
                *(float4*)WS(pn, ld_k, ld_f * 8)     = wreg[0];
                *(float4*)WS(pn, ld_k, ld_f * 8 + 4) = wreg[1];
                __syncthreads();
            }
        }

        // gate tile -> smem (alias over Hs/Ws; GEMM smem reads all done)
        __syncthreads();
        float (*Gsm)[68] = (float (*)[68])sm;
        #pragma unroll
        for (int i = 0; i < 2; i++) {
            float2 p0 = upk(acc[i][0]);
            float2 p1 = upk(acc[i][1]);
            float2 p2 = upk(acc[i][2]);
            float2 p3 = upk(acc[i][3]);
            *(float4*)&Gsm[ty * 2 + i][cg * 8] =
                make_float4(p0.x, p0.y, p1.x, p1.y);
            *(float4*)&Gsm[ty * 2 + i][cg * 8 + 4] =
                make_float4(p2.x, p2.y, p3.x, p3.y);
        }
        __syncthreads();

        // cell update: thread -> (batch cb, units u0+ub .. +3)
        {
            const int s = dir ? (TT - 1 - t) : t;
            const float* xpb = &g_xp[s][cb][dir * GG];
            float gq[4][4];
            #pragma unroll
            for (int q = 0; q < 4; q++) {
                float4 xv = __ldg((const float4*)&xpb[q * HH + u0 + ub]);
                float4 sv = *(const float4*)&Gsm[cb][q * 16 + ub];
                gq[q][0] = xv.x + sv.x; gq[q][1] = xv.y + sv.y;
                gq[q][2] = xv.z + sv.z; gq[q][3] = xv.w + sv.w;
            }
            float4 cv = __ldcg((const float4*)&g_c[dir][cb][u0 + ub]);
            float cold[4] = {cv.x, cv.y, cv.z, cv.w};
            float hn[4], cn[4];
            #pragma unroll
            for (int j = 0; j < 4; j++) {
                float ig = sigm(gq[0][j]);
                float fg = sigm(gq[1][j]);
                float og = sigm(gq[3][j]);
                cn[j] = fg * cold[j] + ig * tanhf(gq[2][j]);
                hn[j] = og * tanhf(cn[j]);
            }
            __stcg((float4*)&g_c[dir][cb][u0 + ub],
                   make_float4(cn[0], cn[1], cn[2], cn[3]));
            #pragma unroll
            for (int j = 0; j < 4; j++)
                __stcg(&g_hT[wr][dir][u0 + ub + j][cb], hn[j]);
            float* op = &out[((size_t)cb * TT + t) * (2 * HH) + dir * HH + u0 + ub];
            *(float4*)op = make_float4(hn[0], hn[1], hn[2], hn[3]);
        }

        // grid barrier
        __syncthreads();
        if (tid == 0) {
            __threadfence();
            atomicAdd(&g_bar, 1u);
            const unsigned target = (unsigned)(t + 1) * NBLK;
            while (*(volatile unsigned*)&g_bar < target) { }
            __threadfence();
        }
        __syncthreads();
    }
    #undef HS
    #undef WS
}

// ---------------------------------------------------------------------------
__global__ void write_tails(float* __restrict__ out) {
    const size_t base = (size_t)BB * TT * 2 * HH;
    int idx = blockIdx.x * blockDim.x + threadIdx.x;
    if (idx < BB * HH) {
        int b = idx / HH;
        int j = idx % HH;
        out[base + 0 * BB * HH + idx] = g_hT[0][0][j][b];  // h_fw
        out[base + 1 * BB * HH + idx] = g_c[0][b][j];      // c_fw
        out[base + 2 * BB * HH + idx] = g_hT[0][1][j][b];  // h_bw
        out[base + 3 * BB * HH + idx] = g_c[1][b][j];      // c_bw
    }
}

// ---------------------------------------------------------------------------
extern "C" void kernel_launch(void* const* d_in, const int* in_sizes, int n_in,
                              void* d_out, int out_size)
{
    const float* x       = (const float*)d_in[0];
    const float* w_ih_fw = (const float*)d_in[1];
    const float* w_hh_fw = (const float*)d_in[2];
    const float* b_ih_fw = (const float*)d_in[3];
    const float* b_hh_fw = (const float*)d_in[4];
    const float* w_ih_bw = (const float*)d_in[5];
    const float* w_hh_bw = (const float*)d_in[6];
    const float* b_ih_bw = (const float*)d_in[7];
    const float* b_hh_bw = (const float*)d_in[8];
    float* out = (float*)d_out;

    init_state<<<1024, 256>>>();
    transpose_w<<<(2 * HH * GG + 255) / 256, 256>>>(w_hh_fw, w_hh_bw);
    xp_gemm<<<dim3(32, 256, 2), 256>>>(x, w_ih_fw, w_ih_bw,
                                       b_ih_fw, b_hh_fw, b_ih_bw, b_hh_bw);
    lstm_persist<<<NBLK, NTHR>>>(out);
    write_tails<<<(BB * HH + 255) / 256, 256>>>(out);
}

// round 13
// speedup vs baseline: 1.7407x; 1.7407x over previous
#include <cuda_runtime.h>

// Problem constants
#define BB 64
#define TT 512
#define II 512
#define HH 1024
#define GG 4096   // 4*H
#define CH 32     // k per smem chunk
#define NCH (HH / CH)
#define NBLK 128
#define NTHR 128

// ---------------------------------------------------------------------------
// Device scratch (static — no allocations allowed)
// ---------------------------------------------------------------------------
__device__ float g_xp[TT][BB][2 * GG];     // 1 GB: input projection + biases
__device__ float g_hTd[2][2][HH][2 * BB];  // [parity][dir][k][2b] h DUPLICATED pairs
__device__ float g_c[2][BB][HH];           // [dir][b][u]
__device__ float g_wT[2][HH][GG];          // w_hh transposed + column-permuted
__device__ unsigned g_bar;                 // grid barrier arrival counter

// ---------------------------------------------------------------------------
// FFMA2 helpers (packed f32x2)
// ---------------------------------------------------------------------------
__device__ __forceinline__ void fma2(unsigned long long& d,
                                     unsigned long long a, unsigned long long b) {
    asm("fma.rn.f32x2 %0, %1, %2, %0;" : "+l"(d) : "l"(a), "l"(b));
}
__device__ __forceinline__ unsigned long long pk2(float lo, float hi) {
    unsigned long long r;
    asm("mov.b64 %0, {%1, %2};" : "=l"(r) : "f"(lo), "f"(hi));
    return r;
}
__device__ __forceinline__ float2 upk(unsigned long long v) {
    float2 f;
    asm("mov.b64 {%0, %1}, %2;" : "=f"(f.x), "=f"(f.y) : "l"(v));
    return f;
}
__device__ __forceinline__ float sigm(float x) {
    return 1.f / (1.f + __expf(-x));
}

// ---------------------------------------------------------------------------
__global__ void init_state() {
    int idx = blockIdx.x * blockDim.x + threadIdx.x;
    const int n_h = 2 * 2 * HH * 2 * BB;   // 524288
    const int n_c = 2 * BB * HH;           // 131072
    if (idx < n_h) ((float*)g_hTd)[idx] = 0.f;
    if (idx < n_c) ((float*)g_c)[idx] = 0.f;
    if (idx == 0) g_bar = 0u;
}

// ---------------------------------------------------------------------------
// One-time w_hh transpose into g_wT[dir][k][pc]:
//   pc = ublock*64 + q*16 + u  <->  src_row = q*H + ublock*16 + u
// ---------------------------------------------------------------------------
__global__ void transpose_w(const float* __restrict__ fw,
                            const float* __restrict__ bw) {
    int idx = blockIdx.x * blockDim.x + threadIdx.x;
    if (idx >= 2 * HH * GG) return;
    int dir = idx / (HH * GG);
    int rem = idx % (HH * GG);
    int k  = rem / GG;
    int pc = rem % GG;
    int ublock = pc >> 6;
    int r2 = pc & 63;
    int q = r2 >> 4;
    int u = r2 & 15;
    int src_row = q * HH + ublock * 16 + u;
    const float* w = dir ? bw : fw;
    g_wT[dir][k][pc] = w[(size_t)src_row * HH + k];
}

// ---------------------------------------------------------------------------
// xp GEMM with column-packed FFMA2 (known-good):
// ---------------------------------------------------------------------------
__global__ __launch_bounds__(256) void xp_gemm(
    const float* __restrict__ x,
    const float* __restrict__ w_fw, const float* __restrict__ w_bw,
    const float* __restrict__ bih_fw, const float* __restrict__ bhh_fw,
    const float* __restrict__ bih_bw, const float* __restrict__ bhh_bw)
{
    const int dir = blockIdx.z;
    const float* __restrict__ w  = dir ? w_bw  : w_fw;
    const float* __restrict__ bi = dir ? bih_bw : bih_fw;
    const float* __restrict__ bh = dir ? bhh_bw : bhh_fw;
    const int n0 = blockIdx.x * 128;
    const int m0 = blockIdx.y * 128;

    __shared__ __align__(16) float As[16][128];
    __shared__ __align__(16) float Bs[16][128];

    const int tid = threadIdx.x;
    const int tx = tid & 15;
    const int ty = tid >> 4;

    unsigned long long acc2[8][4];
    #pragma unroll
    for (int i = 0; i < 8; i++)
        #pragma unroll
        for (int j = 0; j < 4; j++) acc2[i][j] = 0ULL;

    for (int k0 = 0; k0 < II; k0 += 16) {
        #pragma unroll
        for (int it = 0; it < 2; it++) {
            int idx = tid + it * 256;
            int row = idx >> 2;
            int kv  = (idx & 3) * 4;
            int m = m0 + row;
            int s = m >> 6;
            int b = m & 63;
            float4 va = *reinterpret_cast<const float4*>(
                x + ((size_t)b * TT + s) * II + k0 + kv);
            As[kv + 0][row] = va.x; As[kv + 1][row] = va.y;
            As[kv + 2][row] = va.z; As[kv + 3][row] = va.w;
            float4 vb = *reinterpret_cast<const float4*>(
                w + (size_t)(n0 + row) * II + k0 + kv);
            Bs[kv + 0][row] = vb.x; Bs[kv + 1][row] = vb.y;
            Bs[kv + 2][row] = vb.z; Bs[kv + 3][row] = vb.w;
        }
        __syncthreads();
        #pragma unroll
        for (int kk = 0; kk < 16; kk++) {
            float4 a0 = *reinterpret_cast<const float4*>(&As[kk][ty * 8]);
            float4 a1 = *reinterpret_cast<const float4*>(&As[kk][ty * 8 + 4]);
            ulonglong2 b0 = *reinterpret_cast<const ulonglong2*>(&Bs[kk][tx * 8]);
            ulonglong2 b1 = *reinterpret_cast<const ulonglong2*>(&Bs[kk][tx * 8 + 4]);
            float a[8] = {a0.x, a0.y, a0.z, a0.w, a1.x, a1.y, a1.z, a1.w};
            #pragma unroll
            for (int i = 0; i < 8; i++) {
                unsigned long long ap = pk2(a[i], a[i]);
                fma2(acc2[i][0], ap, b0.x);
                fma2(acc2[i][1], ap, b0.y);
                fma2(acc2[i][2], ap, b1.x);
                fma2(acc2[i][3], ap, b1.y);
            }
        }
        __syncthreads();
    }

    float bias[8];
    #pragma unroll
    for (int j = 0; j < 8; j++) {
        int n = n0 + tx * 8 + j;
        bias[j] = bi[n] + bh[n];
    }
    #pragma unroll
    for (int i = 0; i < 8; i++) {
        int m = m0 + ty * 8 + i;
        int s = m >> 6;
        int b = m & 63;
        float2 p0 = upk(acc2[i][0]);
        float2 p1 = upk(acc2[i][1]);
        float2 p2 = upk(acc2[i][2]);
        float2 p3 = upk(acc2[i][3]);
        float* dst = &g_xp[s][b][dir * GG + n0 + tx * 8];
        float4 v0, v1;
        v0.x = p0.x + bias[0]; v0.y = p0.y + bias[1];
        v0.z = p1.x + bias[2]; v0.w = p1.y + bias[3];
        v1.x = p2.x + bias[4]; v1.y = p2.y + bias[5];
        v1.z = p3.x + bias[6]; v1.w = p3.y + bias[7];
        *reinterpret_cast<float4*>(dst)     = v0;
        *reinterpret_cast<float4*>(dst + 4) = v1;
    }
}

// ---------------------------------------------------------------------------
// Persistent recurrence kernel: 128 blocks x 128 threads.
// Block = (dir, 16 hidden units) -> 64x64 gate tile, K=1024.
// Inner loop/k: 2 LDS (h dup pairs, identity layout — reads are broadcast
// conflict-free) + 2 LDS (w col-pairs, swizzled conflict-free) + 16 FFMA2.
// ---------------------------------------------------------------------------
#define HSTR 136   // Hs row stride (floats), 128 data + pad
#define WSTR 72    // Ws row stride (floats), 64 data + swizzle pad

__global__ __launch_bounds__(NTHR, 1) void lstm_persist(float* __restrict__ out)
{
    const int bid = blockIdx.x;
    const int dir = bid >> 6;
    const int ublk = bid & 63;
    const int u0 = ublk * 16;
    const int c0w = ublk * 64;
    const int tid = threadIdx.x;

    // Flat smem: Hs[2][CH][HSTR] @ 0, Ws[2][CH][WSTR] after.
    __shared__ __align__(16) float sm[2 * CH * HSTR + 2 * CH * WSTR];
    #define HS(p, k, i) (sm + (p) * (CH * HSTR) + (k) * HSTR + (i))
    #define WS(p, k, i) (sm + 2 * CH * HSTR + (p) * (CH * WSTR) + (k) * WSTR + (i))

    // staging map: ld_k4 = tid>>4 (0..7), ld_f = tid&15; rows ld_k4*4+r.
    const int ld_k4 = tid >> 4;
    const int ld_f  = tid & 15;
    // H staging: identity (ld_f covers dup floats ld_f*8..+7)
    const int hpos = ld_f * 8;
    // W staging: swizzled (verified consistent + conflict-free)
    const int wpos = ld_f * 4 + (ld_f >= 8 ? 4 : 0);

    // compute map: 8 col-groups x 16 batch-groups
    const int cg = tid & 7;       // cols cg*8 .. +7
    const int ty = tid >> 3;      // batches ty*4 .. +3
    const int hrd = ty * 8;                       // identity H read base
    const int wrd = cg * 8 + (cg >= 4 ? 4 : 0);   // swizzled W read base

    // cell map: 2 threads per batch, 8 units each
    const int cb = tid >> 1;
    const int ub = (tid & 1) * 8;

    for (int t = 0; t < TT; t++) {
        const int rd = t & 1;
        const int wr = rd ^ 1;

        unsigned long long acc[4][4];   // [batch][col-pair]
        #pragma unroll
        for (int i = 0; i < 4; i++)
            #pragma unroll
            for (int j = 0; j < 4; j++) acc[i][j] = 0ULL;

        float4 hreg[8], wreg[4];

        // prologue: stage chunk 0
        #pragma unroll
        for (int r = 0; r < 4; r++) {
            int kk = ld_k4 * 4 + r;
            hreg[2*r]   = __ldcg((const float4*)&g_hTd[rd][dir][kk][ld_f * 8]);
            hreg[2*r+1] = __ldcg((const float4*)&g_hTd[rd][dir][kk][ld_f * 8 + 4]);
            wreg[r] = *(const float4*)&g_wT[dir][kk][c0w + ld_f * 4];
        }
        #pragma unroll
        for (int r = 0; r < 4; r++) {
            int kk = ld_k4 * 4 + r;
            *(float4*)HS(0, kk, hpos)     = hreg[2*r];
            *(float4*)HS(0, kk, hpos + 4) = hreg[2*r+1];
            *(float4*)WS(0, kk, wpos)     = wreg[r];
        }
        __syncthreads();

        for (int c = 0; c < NCH; c++) {
            const int p = c & 1;
            if (c + 1 < NCH) {
                int k0 = (c + 1) * CH;
                #pragma unroll
                for (int r = 0; r < 4; r++) {
                    int kk = k0 + ld_k4 * 4 + r;
                    hreg[2*r]   = __ldcg((const float4*)&g_hTd[rd][dir][kk][ld_f * 8]);
                    hreg[2*r+1] = __ldcg((const float4*)&g_hTd[rd][dir][kk][ld_f * 8 + 4]);
                    wreg[r] = *(const float4*)&g_wT[dir][kk][c0w + ld_f * 4];
                }
            }
            #pragma unroll
            for (int k = 0; k < CH; k++) {
                ulonglong2 a01 = *(const ulonglong2*)HS(p, k, hrd);      // (b0,b0)(b1,b1)
                ulonglong2 a23 = *(const ulonglong2*)HS(p, k, hrd + 4);  // (b2,b2)(b3,b3)
                ulonglong2 w0 = *(const ulonglong2*)WS(p, k, wrd);       // (c0,c1)(c2,c3)
                ulonglong2 w1 = *(const ulonglong2*)WS(p, k, wrd + 4);   // (c4,c5)(c6,c7)
                fma2(acc[0][0], a01.x, w0.x); fma2(acc[0][1], a01.x, w0.y);
                fma2(acc[0][2], a01.x, w1.x); fma2(acc[0][3], a01.x, w1.y);
                fma2(acc[1][0], a01.y, w0.x); fma2(acc[1][1], a01.y, w0.y);
                fma2(acc[1][2], a01.y, w1.x); fma2(acc[1][3], a01.y, w1.y);
                fma2(acc[2][0], a23.x, w0.x); fma2(acc[2][1], a23.x, w0.y);
                fma2(acc[2][2], a23.x, w1.x); fma2(acc[2][3], a23.x, w1.y);
                fma2(acc[3][0], a23.y, w0.x); fma2(acc[3][1], a23.y, w0.y);
                fma2(acc[3][2], a23.y, w1.x); fma2(acc[3][3], a23.y, w1.y);
            }
            if (c + 1 < NCH) {
                __syncthreads();
                const int pn = p ^ 1;
                #pragma unroll
                for (int r = 0; r < 4; r++) {
                    int kk = ld_k4 * 4 + r;
                    *(float4*)HS(pn, kk, hpos)     = hreg[2*r];
                    *(float4*)HS(pn, kk, hpos + 4) = hreg[2*r+1];
                    *(float4*)WS(pn, kk, wpos)     = wreg[r];
                }
                __syncthreads();
            }
        }

        // gate tile -> smem (alias over Hs region; GEMM smem reads all done)
        __syncthreads();
        float (*Gsm)[68] = (float (*)[68])sm;
        #pragma unroll
        for (int i = 0; i < 4; i++) {
            float2 p0 = upk(acc[i][0]);
            float2 p1 = upk(acc[i][1]);
            float2 p2 = upk(acc[i][2]);
            float2 p3 = upk(acc[i][3]);
            *(float4*)&Gsm[ty * 4 + i][cg * 8] =
                make_float4(p0.x, p0.y, p1.x, p1.y);
            *(float4*)&Gsm[ty * 4 + i][cg * 8 + 4] =
                make_float4(p2.x, p2.y, p3.x, p3.y);
        }
        __syncthreads();

        // cell update: thread -> (batch cb, units u0+ub .. +7)
        {
            const int s = dir ? (TT - 1 - t) : t;
            const float* xpb = &g_xp[s][cb][dir * GG];
            float gq[4][8];
            #pragma unroll
            for (int q = 0; q < 4; q++) {
                float4 x0 = __ldg((const float4*)&xpb[q * HH + u0 + ub]);
                float4 x1 = __ldg((const float4*)&xpb[q * HH + u0 + ub + 4]);
                float4 s0 = *(const float4*)&Gsm[cb][q * 16 + ub];
                float4 s1 = *(const float4*)&Gsm[cb][q * 16 + ub + 4];
                gq[q][0] = x0.x + s0.x; gq[q][1] = x0.y + s0.y;
                gq[q][2] = x0.z + s0.z; gq[q][3] = x0.w + s0.w;
                gq[q][4] = x1.x + s1.x; gq[q][5] = x1.y + s1.y;
                gq[q][6] = x1.z + s1.z; gq[q][7] = x1.w + s1.w;
            }
            float4 cv0 = __ldcg((const float4*)&g_c[dir][cb][u0 + ub]);
            float4 cv1 = __ldcg((const float4*)&g_c[dir][cb][u0 + ub + 4]);
            float cold[8] = {cv0.x, cv0.y, cv0.z, cv0.w, cv1.x, cv1.y, cv1.z, cv1.w};
            float hn[8], cn[8];
            #pragma unroll
            for (int j = 0; j < 8; j++) {
                float ig = sigm(gq[0][j]);
                float fg = sigm(gq[1][j]);
                float og = sigm(gq[3][j]);
                cn[j] = fg * cold[j] + ig * tanhf(gq[2][j]);
                hn[j] = og * tanhf(cn[j]);
            }
            __stcg((float4*)&g_c[dir][cb][u0 + ub],
                   make_float4(cn[0], cn[1], cn[2], cn[3]));
            __stcg((float4*)&g_c[dir][cb][u0 + ub + 4],
                   make_float4(cn[4], cn[5], cn[6], cn[7]));
            #pragma unroll
            for (int j = 0; j < 8; j++)
                __stcg((float2*)&g_hTd[wr][dir][u0 + ub + j][2 * cb],
                       make_float2(hn[j], hn[j]));
            float* op = &out[((size_t)cb * TT + t) * (2 * HH) + dir * HH + u0 + ub];
            *(float4*)op       = make_float4(hn[0], hn[1], hn[2], hn[3]);
            *(float4*)(op + 4) = make_float4(hn[4], hn[5], hn[6], hn[7]);
        }

        // grid barrier
        __syncthreads();
        if (tid == 0) {
            __threadfence();
            atomicAdd(&g_bar, 1u);
            const unsigned target = (unsigned)(t + 1) * NBLK;
            while (*(volatile unsigned*)&g_bar < target) { }
            __threadfence();
        }
        __syncthreads();
    }
    #undef HS
    #undef WS
}

// ---------------------------------------------------------------------------
__global__ void write_tails(float* __restrict__ out) {
    const size_t base = (size_t)BB * TT * 2 * HH;
    int idx = blockIdx.x * blockDim.x + threadIdx.x;
    if (idx < BB * HH) {
        int b = idx / HH;
        int j = idx % HH;
        out[base + 0 * BB * HH + idx] = g_hTd[0][0][j][2 * b];  // h_fw
        out[base + 1 * BB * HH + idx] = g_c[0][b][j];           // c_fw
        out[base + 2 * BB * HH + idx] = g_hTd[0][1][j][2 * b];  // h_bw
        out[base + 3 * BB * HH + idx] = g_c[1][b][j];           // c_bw
    }
}

// ---------------------------------------------------------------------------
extern "C" void kernel_launch(void* const* d_in, const int* in_sizes, int n_in,
                              void* d_out, int out_size)
{
    const float* x       = (const float*)d_in[0];
    const float* w_ih_fw = (const float*)d_in[1];
    const float* w_hh_fw = (const float*)d_in[2];
    const float* b_ih_fw = (const float*)d_in[3];
    const float* b_hh_fw = (const float*)d_in[4];
    const float* w_ih_bw = (const float*)d_in[5];
    const float* w_hh_bw = (const float*)d_in[6];
    const float* b_ih_bw = (const float*)d_in[7];
    const float* b_hh_bw = (const float*)d_in[8];
    float* out = (float*)d_out;

    init_state<<<2048, 256>>>();
    transpose_w<<<(2 * HH * GG + 255) / 256, 256>>>(w_hh_fw, w_hh_bw);
    xp_gemm<<<dim3(32, 256, 2), 256>>>(x, w_ih_fw, w_ih_bw,
                                       b_ih_fw, b_hh_fw, b_ih_bw, b_hh_bw);
    lstm_persist<<<NBLK, NTHR>>>(out);
    write_tails<<<(BB * HH + 255) / 256, 256>>>(out);
}